// round 15
// baseline (speedup 1.0000x reference)
#include <cuda_runtime.h>
#include <cuda_fp16.h>
#include <cstdint>

// ============================================================================
// IWConLoss on GB300 (sm_103a via compute_103 baseline PTX):
//   scores = Q @ Neg^T / tau ; loss = mean( LSE_row(scores) - (Q.P)/tau )
// R14: WARP SPECIALIZATION. Warps 0-3 = pure GEMM (A reg-hoisted, fp16 C
// staged to smem, no MUFU in stream). Warps 4-7 = softmax (LSE + prefetch).
// mbarrier pipelines: neg[2 stages], C[2 stages, 16KB XOR-swizzled].
// Each softmax lane owns one row -> shuffle-free LSE. occ 2.
// ============================================================================

static constexpr int NQ   = 8192;
static constexpr int NNEG = 16384;
static constexpr int KD   = 128;

static constexpr int MB = 128;      // query rows per CTA
static constexpr int NT = 64;       // negatives per tile
static constexpr int SPLITS = 16;   // grid = 64 x 16 = 1024 CTAs
static constexpr int RB = NQ / MB;  // 64 row blocks
static constexpr int TILES = NNEG / SPLITS / NT;   // 16

static constexpr int PITCH = 272;                   // 128 fp16 + 8 pad
static constexpr int QT_BYTES = 128 * PITCH;        // 34816
static constexpr int NT_BYTES = NT * PITCH;         // 17408
static constexpr int CB = QT_BYTES + 2 * NT_BYTES;  // 69632: C stages base
static constexpr int CT_BYTES = 128 * 128;          // 16KB per C stage (fp16)
static constexpr int MBAR = CB + 2 * CT_BYTES;      // 102400
static constexpr int SMEM_TOTAL = MBAR + 64;        // 102464 -> 2 CTAs/SM

static constexpr float INV_TAU = 5.0f;
static constexpr float C_T  = 7.2134752044448170f;  // log2(e)/tau
static constexpr float LN2F = 0.69314718055994531f;

// ---------------- device scratch ----------------
__device__ __align__(16) __half g_qh[NQ * KD];
__device__ __align__(16) __half g_nh[NNEG * KD];
__device__ float g_poslogit[NQ];
__device__ float g_pm[SPLITS * NQ];     // [split][row], log2-domain max
__device__ float g_ps[SPLITS * NQ];
__device__ double g_part[RB];
__device__ int g_rbctr[RB];             // zero-init; reset after use
__device__ int g_ctr;                   // zero-init; reset after use

// ---------------- helpers ----------------
__device__ __forceinline__ uint32_t smem_u32(const void* p) {
    uint32_t a;
    asm("{ .reg .u64 t; cvta.to.shared.u64 t, %1; cvt.u32.u64 %0, t; }"
        : "=r"(a) : "l"(p));
    return a;
}
__device__ __forceinline__ float ex2f(float x) {
    float r; asm("ex2.approx.ftz.f32 %0, %1;" : "=f"(r) : "f"(x)); return r;
}
__device__ __forceinline__ void cpa16(uint32_t dst, const void* src) {
    asm volatile("cp.async.cg.shared.global [%0], [%1], 16;" :: "r"(dst), "l"(src));
}
__device__ __forceinline__ void cpa_arrive(uint32_t mbar) {
    asm volatile("cp.async.mbarrier.arrive.noinc.shared.b64 [%0];"
                 :: "r"(mbar) : "memory");
}
#define MBARRIER_INIT(addr, cnt) \
    asm volatile("mbarrier.init.shared.b64 [%0], %1;" :: "r"((uint32_t)(addr)), "r"((uint32_t)(cnt)) : "memory")
#define MBARRIER_ARRIVE(addr) \
    asm volatile("mbarrier.arrive.shared.b64 _, [%0];" :: "r"((uint32_t)(addr)) : "memory")
#define MBARRIER_WAIT_PARITY(mbar_smem_addr, phase_parity) do { \
    uint32_t _mbar = (uint32_t)(mbar_smem_addr); \
    uint32_t _parity = (uint32_t)(phase_parity); \
    uint32_t _done; \
    asm volatile("{\n\t.reg .pred p;\n\t" \
        "mbarrier.try_wait.parity.acquire.cta.shared::cta.b64 p, [%1], %2;\n\t" \
        "selp.b32 %0, 1, 0, p;\n\t}" \
        : "=r"(_done) : "r"(_mbar), "r"(_parity) : "memory"); \
    if (!_done) { \
        asm volatile("{\n\t.reg .pred P1;\n\t" \
            "WAIT_LOOP_%=:\n\t" \
            "mbarrier.try_wait.parity.acquire.cta.shared::cta.b64 P1, [%0], %1, 0x989680;\n\t" \
            "@P1 bra.uni WAIT_DONE_%=;\n\t" \
            "bra.uni WAIT_LOOP_%=;\n\t" \
            "WAIT_DONE_%=:\n\t}" \
            :: "r"(_mbar), "r"(_parity) : "memory"); \
    } \
} while (0)

__device__ __forceinline__ void ldsm4(uint32_t& r0, uint32_t& r1, uint32_t& r2,
                                      uint32_t& r3, uint32_t addr) {
    asm volatile("ldmatrix.sync.aligned.m8n8.x4.shared.b16 {%0,%1,%2,%3}, [%4];"
        : "=r"(r0), "=r"(r1), "=r"(r2), "=r"(r3) : "r"(addr));
}
__device__ __forceinline__ void mma16816_f16(uint32_t* d, const uint32_t* a,
                                             const uint32_t b0, const uint32_t b1) {
    asm volatile(
        "mma.sync.aligned.m16n8k16.row.col.f16.f16.f16.f16 "
        "{%0,%1}, {%2,%3,%4,%5}, {%6,%7}, {%0,%1};"
        : "+r"(d[0]), "+r"(d[1])
        : "r"(a[0]), "r"(a[1]), "r"(a[2]), "r"(a[3]), "r"(b0), "r"(b1));
}
__device__ __forceinline__ void sts32(uint32_t addr, uint32_t v) {
    asm volatile("st.shared.b32 [%0], %1;" :: "r"(addr), "r"(v) : "memory");
}
__device__ __forceinline__ void lds128(uint4& v, uint32_t addr) {
    asm volatile("ld.shared.v4.u32 {%0,%1,%2,%3}, [%4];"
        : "=r"(v.x), "=r"(v.y), "=r"(v.z), "=r"(v.w) : "r"(addr));
}

// ============================================================================
// combined prep kernel (unchanged)
// ============================================================================
static constexpr int NB_NEG = (NNEG * KD) / 1024;   // 2048 blocks

__global__ void prep_kernel(const float* __restrict__ q, const float* __restrict__ pos,
                            const float* __restrict__ neg) {
    if (blockIdx.x < NB_NEG) {
        int i = (blockIdx.x * 256 + threadIdx.x) * 4;
        float4 v = *reinterpret_cast<const float4*>(neg + i);
        __half2* o = reinterpret_cast<__half2*>(g_nh + i);
        o[0] = __floats2half2_rn(v.x, v.y);
        o[1] = __floats2half2_rn(v.z, v.w);
    } else {
        int b = blockIdx.x - NB_NEG;
        int w = threadIdx.x >> 5, lane = threadIdx.x & 31;
        int row = b * 8 + w;
        const float4 q4 = *reinterpret_cast<const float4*>(q + row * KD + lane * 4);
        const float4 p4 = *reinterpret_cast<const float4*>(pos + row * KD + lane * 4);
        float d = q4.x * p4.x + q4.y * p4.y + q4.z * p4.z + q4.w * p4.w;
        #pragma unroll
        for (int o = 16; o > 0; o >>= 1) d += __shfl_xor_sync(0xffffffffu, d, o);
        if (lane == 0) g_poslogit[row] = d * INV_TAU;

        __half2* o = reinterpret_cast<__half2*>(g_qh + row * KD + lane * 4);
        o[0] = __floats2half2_rn(q4.x * C_T, q4.y * C_T);
        o[1] = __floats2half2_rn(q4.z * C_T, q4.w * C_T);
    }
}

// ============================================================================
// main fused kernel: warps 0-3 GEMM, warps 4-7 softmax/prefetch
// ============================================================================
__device__ __forceinline__ void copy_q_block(uint32_t sb, int stid, int qbase) {
    #pragma unroll
    for (int j = 0; j < 16; j++) {
        int idx = j * 128 + stid;            // 0..2047
        int row = idx >> 4, c = idx & 15;
        cpa16(sb + (uint32_t)(row * PITCH + c * 16), g_qh + (qbase + row) * KD + c * 8);
    }
}
__device__ __forceinline__ void copy_neg_tile(uint32_t sb, int stid, int stage, int rowbase) {
    uint32_t base = sb + (uint32_t)(QT_BYTES + NT_BYTES * stage);
    #pragma unroll
    for (int j = 0; j < 8; j++) {
        int idx = j * 128 + stid;            // 0..1023
        int row = idx >> 4, c = idx & 15;
        cpa16(base + (uint32_t)(row * PITCH + c * 16),
              g_nh + (rowbase + row) * KD + c * 8);
    }
}

__global__ __launch_bounds__(256, 2) void conloss_main_kernel(float* __restrict__ out) {
    extern __shared__ char smem[];
    uint32_t sb = smem_u32(smem);
    const int tid = threadIdx.x, warp = tid >> 5, lane = tid & 31;
    const int rb = blockIdx.x;
    const int qbase = rb * MB;
    const int negbase = blockIdx.y * (NNEG / SPLITS);

    // mbarriers: negF[2](128), negE[2](4), cF[2](128), cE[2](128)
    const uint32_t negF0 = sb + MBAR,      negF1 = sb + MBAR + 8;
    const uint32_t negE0 = sb + MBAR + 16, negE1 = sb + MBAR + 24;
    const uint32_t cF0   = sb + MBAR + 32, cF1   = sb + MBAR + 40;
    const uint32_t cE0   = sb + MBAR + 48, cE1   = sb + MBAR + 56;
    if (tid == 0) {
        MBARRIER_INIT(negF0, 128); MBARRIER_INIT(negF1, 128);
        MBARRIER_INIT(negE0, 4);   MBARRIER_INIT(negE1, 4);
        MBARRIER_INIT(cF0, 128);   MBARRIER_INIT(cF1, 128);
        MBARRIER_INIT(cE0, 128);   MBARRIER_INIT(cE1, 128);
    }
    __syncthreads();

    if (warp >= 4) {
        // ==================== SOFTMAX / PREFETCH group ====================
        const int stid = tid - 128;
        // prologue: Q + tile0 -> negF0 ; tile1 -> negF1
        copy_q_block(sb, stid, qbase);
        copy_neg_tile(sb, stid, 0, negbase);
        cpa_arrive(negF0);
        copy_neg_tile(sb, stid, 1, negbase + NT);
        cpa_arrive(negF1);

        const int g = warp - 4;
        const int R = g * 32 + lane;            // my row (0..127)
        const uint32_t rowA = (uint32_t)(R * 128);
        const uint32_t rsw = (uint32_t)(R & 7);

        float mrun = -1e30f, srun = 0.0f;

        #pragma unroll 1
        for (int t = 0; t < TILES; t++) {
            const int s = t & 1, p = (t >> 1) & 1;
            const uint32_t cBase = sb + (uint32_t)(CB + s * CT_BYTES) + rowA;
            MBARRIER_WAIT_PARITY(s ? cF1 : cF0, p);

            // load my row: 8 swizzled 16B chunks = 64 fp16 scores
            float x[64];
            #pragma unroll
            for (int j = 0; j < 8; j++) {
                uint4 v;
                lds128(v, cBase + (uint32_t)(((uint32_t)j ^ rsw) << 4));
                const uint32_t* u = &v.x;
                #pragma unroll
                for (int q2 = 0; q2 < 4; q2++) {
                    float2 f = __half22float2(*reinterpret_cast<const __half2*>(&u[q2]));
                    x[j * 8 + q2 * 2]     = f.x;
                    x[j * 8 + q2 * 2 + 1] = f.y;
                }
            }
            float tmax = x[0];
            #pragma unroll
            for (int i = 1; i < 64; i++) tmax = fmaxf(tmax, x[i]);
            // all 64 values consumed -> LDS complete -> safe to release C stage
            MBARRIER_ARRIVE(s ? cE1 : cE0);

            if (tmax > mrun) {
                srun *= ex2f(mrun - tmax);
                mrun = tmax;
            }
            float acc = 0.0f;
            #pragma unroll
            for (int i = 0; i < 64; i++) acc += ex2f(x[i] - mrun);
            srun += acc;

            if (t + 2 < TILES) {
                MBARRIER_WAIT_PARITY(s ? negE1 : negE0, p);  // gemm done reading s
                copy_neg_tile(sb, stid, s, negbase + (t + 2) * NT);
                cpa_arrive(s ? negF1 : negF0);
            }
        }
        // direct per-row partial write (one row per lane)
        g_pm[blockIdx.y * NQ + qbase + R] = mrun;
        g_ps[blockIdx.y * NQ + qbase + R] = srun;
        __threadfence();
    } else {
        // ==================== GEMM group ====================
        MBARRIER_WAIT_PARITY(negF0, 0);      // Q + tile0 resident
        // hoist full A (my 32 rows x 128 k) into registers
        const uint32_t aBase = sb + (uint32_t)((warp * 32 + (lane & 15)) * PITCH
                                               + ((lane >> 4) * 16));
        uint32_t A[2][8][4];
        #pragma unroll
        for (int mi = 0; mi < 2; mi++)
            #pragma unroll
            for (int ks = 0; ks < 8; ks++)
                ldsm4(A[mi][ks][0], A[mi][ks][1], A[mi][ks][2], A[mi][ks][3],
                      aBase + (uint32_t)(mi * 16 * PITCH + ks * 32));

        const int wrow = warp * 32;
        const uint32_t bRowOff = (uint32_t)(((lane & 7) + ((lane >> 4) << 3)) * PITCH
                                            + (((lane >> 3) & 1) * 16));
        // C STS addressing (XOR-swizzled, conflict-free)
        const int r0 = wrow + (lane >> 2);
        const uint32_t cCol = (uint32_t)((lane & 3) * 4);

        #pragma unroll 1
        for (int t = 0; t < TILES; t++) {
            const int s = t & 1, p = (t >> 1) & 1;
            if (t > 0) MBARRIER_WAIT_PARITY(s ? negF1 : negF0, p);
            if (t >= 2) MBARRIER_WAIT_PARITY(s ? cE1 : cE0, p ^ 1);

            const uint32_t bStage = sb + (uint32_t)(QT_BYTES + NT_BYTES * s);
            const uint32_t cStage = sb + (uint32_t)(CB + s * CT_BYTES);

            #pragma unroll
            for (int cb = 0; cb < 2; cb++) {       // two 32-col passes
                uint32_t C[2][4][2];
                #pragma unroll
                for (int mi = 0; mi < 2; mi++)
                    #pragma unroll
                    for (int ni = 0; ni < 4; ni++) { C[mi][ni][0] = 0u; C[mi][ni][1] = 0u; }

                #pragma unroll
                for (int ks = 0; ks < 8; ks++) {
                    uint32_t B[2][4];
                    #pragma unroll
                    for (int nb = 0; nb < 2; nb++)
                        ldsm4(B[nb][0], B[nb][1], B[nb][2], B[nb][3],
                              bStage + bRowOff
                              + (uint32_t)((cb * 32 + nb * 16) * PITCH + ks * 32));
                    #pragma unroll
                    for (int mi = 0; mi < 2; mi++)
                        #pragma unroll
                        for (int ni = 0; ni < 4; ni++)
                            mma16816_f16(C[mi][ni], A[mi][ks],
                                         B[ni >> 1][(ni & 1) * 2], B[ni >> 1][(ni & 1) * 2 + 1]);
                }
                // store 32x32 half-tile to C stage (fp16)
                #pragma unroll
                for (int mi = 0; mi < 2; mi++) {
                    #pragma unroll
                    for (int ni = 0; ni < 4; ni++) {
                        const uint32_t j = (uint32_t)(cb * 4 + ni);
                        const int Ra = r0 + mi * 16, Rb2 = Ra + 8;
                        sts32(cStage + (uint32_t)(Ra * 128)
                              + ((j ^ (uint32_t)(Ra & 7)) << 4) + cCol, C[mi][ni][0]);
                        sts32(cStage + (uint32_t)(Rb2 * 128)
                              + ((j ^ (uint32_t)(Rb2 & 7)) << 4) + cCol, C[mi][ni][1]);
                    }
                }
            }
            MBARRIER_ARRIVE(s ? cF1 : cF0);              // C tile ready
            if (lane == 0) MBARRIER_ARRIVE(s ? negE1 : negE0);  // B stage consumed
        }
    }

    // ---------------- fused reduction (common path) ----------------
    __syncthreads();
    __shared__ int lastRb;
    if (tid == 0)
        lastRb = (atomicAdd(&g_rbctr[rb], 1) == SPLITS - 1);
    __syncthreads();
    if (!lastRb) return;

    __threadfence();
    double part = 0.0;
    if (tid < 128) {
        int r = qbase + tid;
        float m[SPLITS], s[SPLITS];
        #pragma unroll
        for (int j = 0; j < SPLITS; j++) {
            m[j] = g_pm[j * NQ + r];
            s[j] = g_ps[j * NQ + r];
        }
        float M = m[0];
        #pragma unroll
        for (int j = 1; j < SPLITS; j++) M = fmaxf(M, m[j]);
        float S = 0.0f;
        #pragma unroll
        for (int j = 0; j < SPLITS; j++) S += s[j] * ex2f(m[j] - M);
        float lse = LN2F * (M + log2f(S));
        part = (double)(lse - g_poslogit[r]);
    }
    double* shd = reinterpret_cast<double*>(smem);   // tiles no longer needed
    shd[tid] = part;
    __syncthreads();
    for (int o = 128; o > 0; o >>= 1) {
        if (tid < o) shd[tid] += shd[tid + o];
        __syncthreads();
    }
    if (tid == 0) {
        g_part[rb] = shd[0];
        g_rbctr[rb] = 0;                 // reset for next graph replay
        __threadfence();
        if (atomicAdd(&g_ctr, 1) == RB - 1) {
            __threadfence();
            double acc = 0.0;
            #pragma unroll
            for (int i = 0; i < RB; i++) acc += g_part[i];
            out[0] = (float)(acc / (double)NQ);
            g_ctr = 0;                   // reset for next graph replay
        }
    }
}

// ============================================================================
// kernel_launch
// ============================================================================
extern "C" void kernel_launch(void* const* d_in, const int* in_sizes, int n_in,
                              void* d_out, int out_size) {
    (void)n_in; (void)out_size;
    const float* a0 = (const float*)d_in[0];
    const float* a1 = (const float*)d_in[1];
    const float* a2 = (const float*)d_in[2];
    const float *q, *p, *neg;
    if (in_sizes[2] == NNEG * KD)      { q = a0; p = a1; neg = a2; }
    else if (in_sizes[1] == NNEG * KD) { q = a0; p = a2; neg = a1; }
    else                               { q = a1; p = a2; neg = a0; }

    cudaFuncSetAttribute(conloss_main_kernel,
                         cudaFuncAttributeMaxDynamicSharedMemorySize, SMEM_TOTAL);

    prep_kernel<<<NB_NEG + NQ / 8, 256>>>(q, p, neg);
    conloss_main_kernel<<<dim3(RB, SPLITS), 256, SMEM_TOTAL>>>((float*)d_out);
}

// round 16
// speedup vs baseline: 1.0709x; 1.0709x over previous
#include <cuda_runtime.h>
#include <cuda_fp16.h>
#include <cstdint>

// ============================================================================
// IWConLoss on GB300 (sm_103a via compute_103 baseline PTX):
//   scores = Q @ Neg^T / tau ; loss = mean( LSE_row(scores) - (Q.P)/tau )
// R15 = R13 (best) + fp16-native epilogue: hmax2/hsub2/h2exp2/hadd2 on the
// packed half2 C fragments (no cvt before exp; MUFU count halved).
// 4-warp CTAs, 32x64 warp tiles, full A-register hoist, occ 3, fp16 HMMA,
// fused counter reduction, 64x16 multi-wave dispatch.
// ============================================================================

static constexpr int NQ   = 8192;
static constexpr int NNEG = 16384;
static constexpr int KD   = 128;

static constexpr int MB = 128;      // query rows per CTA
static constexpr int NT = 64;       // negatives per tile
static constexpr int SPLITS = 16;   // grid = 64 x 16 = 1024 CTAs
static constexpr int RB = NQ / MB;  // 64 row blocks
static constexpr int TILES = NNEG / SPLITS / NT;   // 16
static constexpr int STAGES = 2;

static constexpr int PITCH = 272;                   // 128 fp16 + 8 pad
static constexpr int QT_BYTES = 128 * PITCH;        // 34816
static constexpr int NT_BYTES = NT * PITCH;         // 17408
static constexpr int SMEM_TOTAL = QT_BYTES + STAGES * NT_BYTES;  // 69632 -> occ3

static constexpr float INV_TAU = 5.0f;
static constexpr float C_T  = 7.2134752044448170f;  // log2(e)/tau
static constexpr float LN2F = 0.69314718055994531f;

// ---------------- device scratch ----------------
__device__ __align__(16) __half g_qh[NQ * KD];
__device__ __align__(16) __half g_nh[NNEG * KD];
__device__ float g_poslogit[NQ];
__device__ float g_pm[SPLITS * NQ];     // [split][row]
__device__ float g_ps[SPLITS * NQ];
__device__ double g_part[RB];
__device__ int g_rbctr[RB];             // zero-init; reset after use
__device__ int g_ctr;                   // zero-init; reset after use

// ---------------- helpers ----------------
__device__ __forceinline__ uint32_t smem_u32(const void* p) {
    uint32_t a;
    asm("{ .reg .u64 t; cvta.to.shared.u64 t, %1; cvt.u32.u64 %0, t; }"
        : "=r"(a) : "l"(p));
    return a;
}
__device__ __forceinline__ float ex2f(float x) {
    float r; asm("ex2.approx.ftz.f32 %0, %1;" : "=f"(r) : "f"(x)); return r;
}
__device__ __forceinline__ void cpa16(uint32_t dst, const void* src) {
    asm volatile("cp.async.cg.shared.global [%0], [%1], 16;" :: "r"(dst), "l"(src));
}
#define CP_COMMIT() asm volatile("cp.async.commit_group;" ::: "memory")
#define CP_WAIT(n)  asm volatile("cp.async.wait_group %0;" :: "n"(n) : "memory")

__device__ __forceinline__ void ldsm4(uint32_t& r0, uint32_t& r1, uint32_t& r2,
                                      uint32_t& r3, uint32_t addr) {
    asm volatile("ldmatrix.sync.aligned.m8n8.x4.shared.b16 {%0,%1,%2,%3}, [%4];"
        : "=r"(r0), "=r"(r1), "=r"(r2), "=r"(r3) : "r"(addr));
}
// fp16-accumulator MMA: D,C packed half2
__device__ __forceinline__ void mma16816_f16(uint32_t* d, const uint32_t* a,
                                             const uint32_t b0, const uint32_t b1) {
    asm volatile(
        "mma.sync.aligned.m16n8k16.row.col.f16.f16.f16.f16 "
        "{%0,%1}, {%2,%3,%4,%5}, {%6,%7}, {%0,%1};"
        : "+r"(d[0]), "+r"(d[1])
        : "r"(a[0]), "r"(a[1]), "r"(a[2]), "r"(a[3]), "r"(b0), "r"(b1));
}

// ============================================================================
// combined prep kernel
// ============================================================================
static constexpr int NB_NEG = (NNEG * KD) / 1024;   // 2048 blocks

__global__ void prep_kernel(const float* __restrict__ q, const float* __restrict__ pos,
                            const float* __restrict__ neg) {
    if (blockIdx.x < NB_NEG) {
        int i = (blockIdx.x * 256 + threadIdx.x) * 4;
        float4 v = *reinterpret_cast<const float4*>(neg + i);
        __half2* o = reinterpret_cast<__half2*>(g_nh + i);
        o[0] = __floats2half2_rn(v.x, v.y);
        o[1] = __floats2half2_rn(v.z, v.w);
    } else {
        int b = blockIdx.x - NB_NEG;
        int w = threadIdx.x >> 5, lane = threadIdx.x & 31;
        int row = b * 8 + w;
        const float4 q4 = *reinterpret_cast<const float4*>(q + row * KD + lane * 4);
        const float4 p4 = *reinterpret_cast<const float4*>(pos + row * KD + lane * 4);
        float d = q4.x * p4.x + q4.y * p4.y + q4.z * p4.z + q4.w * p4.w;
        #pragma unroll
        for (int o = 16; o > 0; o >>= 1) d += __shfl_xor_sync(0xffffffffu, d, o);
        if (lane == 0) g_poslogit[row] = d * INV_TAU;

        __half2* o = reinterpret_cast<__half2*>(g_qh + row * KD + lane * 4);
        o[0] = __floats2half2_rn(q4.x * C_T, q4.y * C_T);
        o[1] = __floats2half2_rn(q4.z * C_T, q4.w * C_T);
    }
}

// ============================================================================
// main fused kernel: 128 threads (4 warps), warp tile 32x64
// ============================================================================
__device__ __forceinline__ void copy_q_block(uint32_t sb, int tid, int qbase) {
    #pragma unroll
    for (int j = 0; j < 16; j++) {
        int idx = j * 128 + tid;             // 0..2047
        int row = idx >> 4, c = idx & 15;
        cpa16(sb + (uint32_t)(row * PITCH + c * 16), g_qh + (qbase + row) * KD + c * 8);
    }
}
__device__ __forceinline__ void copy_neg_tile(uint32_t sb, int tid, int stage, int rowbase) {
    uint32_t base = sb + (uint32_t)(QT_BYTES + NT_BYTES * stage);
    #pragma unroll
    for (int j = 0; j < 8; j++) {
        int idx = j * 128 + tid;             // 0..1023
        int row = idx >> 4, c = idx & 15;
        cpa16(base + (uint32_t)(row * PITCH + c * 16),
              g_nh + (rowbase + row) * KD + c * 8);
    }
}

// fp16-native online LSE over one 32x64 warp tile; C packed half2
__device__ __forceinline__ void epilogue(const uint32_t C[2][8][2], float* mrun, float* srun) {
    #pragma unroll
    for (int j = 0; j < 4; j++) {
        const int mi = j >> 1, hi = j & 1;
        __half2 h[8];
        #pragma unroll
        for (int ni = 0; ni < 8; ni++)
            h[ni] = *reinterpret_cast<const __half2*>(&C[mi][ni][hi]);

        // max over 16 values: hmax2 tree + final pair resolve
        __half2 mm = __hmax2(__hmax2(__hmax2(h[0], h[1]), __hmax2(h[2], h[3])),
                             __hmax2(__hmax2(h[4], h[5]), __hmax2(h[6], h[7])));
        float tmax = fmaxf(__low2float(mm), __high2float(mm));
        if (tmax > mrun[j]) {
            srun[j] *= ex2f(mrun[j] - tmax);
            mrun[j] = tmax;
        }
        // exp in fp16x2 (MUFU ex2.f16x2): x - m in [-inf, 0], no overflow
        const __half2 mh = __float2half2_rn(mrun[j]);
        __half2 a0 = __hadd2(h2exp2(__hsub2(h[0], mh)), h2exp2(__hsub2(h[1], mh)));
        __half2 a1 = __hadd2(h2exp2(__hsub2(h[2], mh)), h2exp2(__hsub2(h[3], mh)));
        __half2 a2 = __hadd2(h2exp2(__hsub2(h[4], mh)), h2exp2(__hsub2(h[5], mh)));
        __half2 a3 = __hadd2(h2exp2(__hsub2(h[6], mh)), h2exp2(__hsub2(h[7], mh)));
        __half2 acc = __hadd2(__hadd2(a0, a1), __hadd2(a2, a3));
        float2 f = __half22float2(acc);
        srun[j] += f.x + f.y;
    }
}

__global__ __launch_bounds__(128, 3) void conloss_main_kernel(float* __restrict__ out) {
    extern __shared__ char smem[];
    uint32_t sb = smem_u32(smem);
    const int tid = threadIdx.x, warp = tid >> 5, lane = tid & 31;
    const int rb = blockIdx.x;
    const int qbase = rb * MB;
    const int negbase = blockIdx.y * (NNEG / SPLITS);

    copy_q_block(sb, tid, qbase);
    copy_neg_tile(sb, tid, 0, negbase);
    CP_COMMIT();                                  // group: Q + tile0
    copy_neg_tile(sb, tid, 1, negbase + NT);
    CP_COMMIT();                                  // group: tile1

    // ---- hoist the ENTIRE A (Q) tile into registers (once per CTA) ----
    CP_WAIT(1);                                   // Q + tile0 resident
    __syncthreads();
    const uint32_t aBase = sb + (uint32_t)((warp * 32 + (lane & 15)) * PITCH
                                           + ((lane >> 4) * 16));
    uint32_t A[2][8][4];
    #pragma unroll
    for (int mi = 0; mi < 2; mi++)
        #pragma unroll
        for (int ks = 0; ks < 8; ks++)
            ldsm4(A[mi][ks][0], A[mi][ks][1], A[mi][ks][2], A[mi][ks][3],
                  aBase + (uint32_t)(mi * 16 * PITCH + ks * 32));

    const uint32_t bOff = (uint32_t)(((lane & 7) + ((lane >> 4) << 3)) * PITCH
                                     + (((lane >> 3) & 1) * 16));

    uint32_t C[2][8][2];
    float mrun[4], srun[4];
    #pragma unroll
    for (int j = 0; j < 4; j++) { mrun[j] = -1e30f; srun[j] = 0.0f; }

    #pragma unroll 1
    for (int t = 0; t < TILES; t++) {
        CP_WAIT(STAGES - 1);
        __syncthreads();

        #pragma unroll
        for (int mi = 0; mi < 2; mi++)
            #pragma unroll
            for (int ni = 0; ni < 8; ni++) { C[mi][ni][0] = 0u; C[mi][ni][1] = 0u; }

        const uint32_t bBase = sb + (uint32_t)(QT_BYTES + NT_BYTES * (t & 1)) + bOff;

        #pragma unroll
        for (int ks = 0; ks < 8; ks++) {
            uint32_t B[4][4];                     // 4 col-blocks x 4 regs
            #pragma unroll
            for (int cb = 0; cb < 4; cb++)
                ldsm4(B[cb][0], B[cb][1], B[cb][2], B[cb][3],
                      bBase + (uint32_t)(cb * 16 * PITCH + ks * 32));
            #pragma unroll
            for (int mi = 0; mi < 2; mi++)
                #pragma unroll
                for (int ni = 0; ni < 8; ni++)
                    mma16816_f16(C[mi][ni], A[mi][ks],
                                 B[ni >> 1][(ni & 1) * 2], B[ni >> 1][(ni & 1) * 2 + 1]);
        }
        __syncthreads();

        if (t + STAGES < TILES)
            copy_neg_tile(sb, tid, t & 1, negbase + (t + STAGES) * NT);
        CP_COMMIT();

        epilogue(C, mrun, srun);
    }

    // combine the 4 lanes sharing each row (row fully owned by this warp)
    #pragma unroll
    for (int j = 0; j < 4; j++) {
        #pragma unroll
        for (int off = 1; off <= 2; off <<= 1) {
            float mo = __shfl_xor_sync(0xffffffffu, mrun[j], off);
            float so = __shfl_xor_sync(0xffffffffu, srun[j], off);
            float M = fmaxf(mrun[j], mo);
            srun[j] = srun[j] * ex2f(mrun[j] - M) + so * ex2f(mo - M);
            mrun[j] = M;
        }
    }
    // direct per-row partial write
    if ((lane & 3) == 0) {
        #pragma unroll
        for (int j = 0; j < 4; j++) {
            int row = warp * 32 + (j >> 1) * 16 + (j & 1) * 8 + (lane >> 2);
            g_pm[blockIdx.y * NQ + qbase + row] = mrun[j];
            g_ps[blockIdx.y * NQ + qbase + row] = srun[j];
        }
    }

    // ---------------- fused reduction ----------------
    __threadfence();
    __syncthreads();
    __shared__ int lastRb;
    if (tid == 0)
        lastRb = (atomicAdd(&g_rbctr[rb], 1) == SPLITS - 1);
    __syncthreads();
    if (!lastRb) return;

    __threadfence();
    double part = 0.0;
    {
        int r = qbase + tid;
        float m[SPLITS], s[SPLITS];
        #pragma unroll
        for (int j = 0; j < SPLITS; j++) {
            m[j] = g_pm[j * NQ + r];
            s[j] = g_ps[j * NQ + r];
        }
        float M = m[0];
        #pragma unroll
        for (int j = 1; j < SPLITS; j++) M = fmaxf(M, m[j]);
        float S = 0.0f;
        #pragma unroll
        for (int j = 0; j < SPLITS; j++) S += s[j] * ex2f(m[j] - M);
        float lse = LN2F * (M + log2f(S));
        part = (double)(lse - g_poslogit[r]);
    }
    double* shd = reinterpret_cast<double*>(smem);   // tiles no longer needed
    shd[tid] = part;
    __syncthreads();
    for (int o = 64; o > 0; o >>= 1) {
        if (tid < o) shd[tid] += shd[tid + o];
        __syncthreads();
    }
    if (tid == 0) {
        g_part[rb] = shd[0];
        g_rbctr[rb] = 0;                 // reset for next graph replay
        __threadfence();
        if (atomicAdd(&g_ctr, 1) == RB - 1) {
            __threadfence();
            double acc = 0.0;
            #pragma unroll
            for (int i = 0; i < RB; i++) acc += g_part[i];
            out[0] = (float)(acc / (double)NQ);
            g_ctr = 0;                   // reset for next graph replay
        }
    }
}

// ============================================================================
// kernel_launch
// ============================================================================
extern "C" void kernel_launch(void* const* d_in, const int* in_sizes, int n_in,
                              void* d_out, int out_size) {
    (void)n_in; (void)out_size;
    const float* a0 = (const float*)d_in[0];
    const float* a1 = (const float*)d_in[1];
    const float* a2 = (const float*)d_in[2];
    const float *q, *p, *neg;
    if (in_sizes[2] == NNEG * KD)      { q = a0; p = a1; neg = a2; }
    else if (in_sizes[1] == NNEG * KD) { q = a0; p = a2; neg = a1; }
    else                               { q = a1; p = a2; neg = a0; }

    cudaFuncSetAttribute(conloss_main_kernel,
                         cudaFuncAttributeMaxDynamicSharedMemorySize, SMEM_TOTAL);

    prep_kernel<<<NB_NEG + NQ / 8, 256>>>(q, p, neg);
    conloss_main_kernel<<<dim3(RB, SPLITS), 128, SMEM_TOTAL>>>((float*)d_out);
}